// round 7
// baseline (speedup 1.0000x reference)
#include <cuda_runtime.h>
#include <cstdint>

#define N_NODES 100000
#define N_EDGES 1600000

// ---------------- scratch (static device globals; no allocations) ----------------
__device__ int   g_is64;
__device__ float g_deg[N_NODES];
__device__ int   g_counts[N_NODES];
__device__ int   g_rowptr[N_NODES + 1];
__device__ int   g_cursor[N_NODES];
__device__ int2  g_edge[N_EDGES];          // {src, norm_bits}
__device__ float g_bufA[(size_t)N_NODES * 128];
__device__ float g_bufB[(size_t)N_NODES * 128];
// W fragments (hi/lo): W1@0 (16384), W2@16384, W3@32768 (8192)
__device__ float g_wh[40960];
__device__ float g_wl[40960];

// ---------------- fused: dtype detection + init ----------------
__global__ void k_detect_init(const int* __restrict__ w) {
    int i = blockIdx.x * blockDim.x + threadIdx.x;
    if (i < N_NODES) { g_deg[i] = 1.0f; g_counts[i] = 0; }
    if (blockIdx.x == 0) {
        __shared__ int any;
        if (threadIdx.x == 0) any = 0;
        __syncthreads();
        const int STRIDE = N_EDGES / 4096;
        for (int t = threadIdx.x; t < 4096; t += blockDim.x) {
            int v = w[2 * (t * STRIDE) + 1];
            if (v != 0) any = 1;
        }
        __syncthreads();
        if (threadIdx.x == 0) g_is64 = any ? 0 : 1;
    }
}

__device__ __forceinline__ int load_idx(const void* ei, long long pos) {
    if (g_is64) return (int)((const long long*)ei)[pos];
    return ((const int*)ei)[pos];
}

// ---------------- prep kernels ----------------
__global__ void k_deg(const void* __restrict__ ei, const float* __restrict__ ew) {
    int e = blockIdx.x * blockDim.x + threadIdx.x;
    if (e < N_EDGES) {
        int dst = load_idx(ei, (long long)N_EDGES + e);
        atomicAdd(&g_deg[dst], ew[e]);
        atomicAdd(&g_counts[dst], 1);
    }
}

__global__ void k_scan() {
    __shared__ int sbuf[2][1024];
    const int tid = threadIdx.x;
    const int per = (N_NODES + 1023) / 1024;
    int start = tid * per;
    int end   = min(start + per, N_NODES);

    int s = 0;
    for (int i = start; i < end; i++) s += g_counts[i];

    int sel = 0;
    sbuf[0][tid] = s;
    __syncthreads();
    for (int off = 1; off < 1024; off <<= 1) {
        int v = sbuf[sel][tid];
        if (tid >= off) v += sbuf[sel][tid - off];
        sbuf[sel ^ 1][tid] = v;
        sel ^= 1;
        __syncthreads();
    }
    int incl = sbuf[sel][tid];
    int run  = incl - s;
    for (int i = start; i < end; i++) {
        g_rowptr[i] = run;
        g_cursor[i] = run;
        run += g_counts[i];
    }
    if (end == N_NODES) g_rowptr[N_NODES] = run;
}

__global__ void k_scatter(const void* __restrict__ ei, const float* __restrict__ ew) {
    int e = blockIdx.x * blockDim.x + threadIdx.x;
    if (e < N_EDGES) {
        int src = load_idx(ei, e);
        int dst = load_idx(ei, (long long)N_EDGES + e);
        int p = atomicAdd(&g_cursor[dst], 1);
        float norm = rsqrtf(g_deg[src]) * ew[e] * rsqrtf(g_deg[dst]);
        g_edge[p] = make_int2(src, __float_as_int(norm));
    }
}

// ---------------- W fragment rearrangement (all 3 weights, one launch) ----------------
template <int N>
__device__ __forceinline__ void wfrag_body(const float* __restrict__ W,
                                           float* __restrict__ outh,
                                           float* __restrict__ outl, int blk) {
    constexpr int NT2 = N / 16;
    int tid = blk * 256 + threadIdx.x;
    if (tid >= 16 * NT2 * 32) return;
    int lane = tid & 31;
    int idx  = tid >> 5;
    int nt2  = idx % NT2;
    int ks   = idx / NT2;
    #pragma unroll
    for (int u = 0; u < 2; u++) {
        #pragma unroll
        for (int j = 0; j < 2; j++) {
            int k = ks * 8 + (lane & 3) + j * 4;
            int n = (nt2 * 2 + u) * 8 + (lane >> 2);
            float v = W[k * N + n];
            unsigned hb = __float_as_uint(v) & 0xFFFFE000u;
            float hi = __uint_as_float(hb);
            outh[tid * 4 + u * 2 + j] = hi;
            outl[tid * 4 + u * 2 + j] = v - hi;
        }
    }
}

__global__ void k_wfrag_all(const float* __restrict__ W1, const float* __restrict__ W2,
                            const float* __restrict__ W3) {
    int b = blockIdx.x;
    if (b < 16)      wfrag_body<128>(W1, g_wh,         g_wl,         b);
    else if (b < 32) wfrag_body<128>(W2, g_wh + 16384, g_wl + 16384, b - 16);
    else             wfrag_body<64>(W3,  g_wh + 32768, g_wl + 32768, b - 32);
}

// ---------------- tensor-core GEMM: Y[M,N] = X[M,128] @ W[128,N], 3xTF32 ----------------
// 256 threads, BM=64. A tile pre-split hi/lo in smem; W frags hi/lo in smem.
#define MMA_TF32(D, A, B)                                                      \
    asm volatile(                                                              \
        "mma.sync.aligned.m16n8k8.row.col.f32.tf32.tf32.f32 "                  \
        "{%0,%1,%2,%3},{%4,%5,%6,%7},{%8,%9},{%0,%1,%2,%3};\n"                 \
        : "+f"(D[0]), "+f"(D[1]), "+f"(D[2]), "+f"(D[3])                       \
        : "r"(A[0]), "r"(A[1]), "r"(A[2]), "r"(A[3]), "r"(B[0]), "r"(B[1]))

template <int N>
__global__ void __launch_bounds__(256, 1)
k_gemm_tc(const float* __restrict__ X, const float* __restrict__ Wh,
          const float* __restrict__ Wl, float* __restrict__ Y) {
    constexpr int KS = 16, NT2 = N / 16;
    constexpr int WN = N / 32;                 // warps along N
    constexpr int MT = (N == 128) ? 2 : 1;     // 16-row m-tiles per warp
    constexpr int WSZ = KS * NT2 * 128;        // frag floats per W variant
    constexpr int BM = 64, XROW = 132, XSZ = BM * XROW;
    constexpr int PF = 8;                      // float4 per thread per X tile

    extern __shared__ float sm[];
    float* wsh  = sm;
    float* wsl  = sm + WSZ;
    float* xs_h = sm + 2 * WSZ;                // [BM][XROW] hi
    float* xs_l = sm + 2 * WSZ + XSZ;          // [BM][XROW] lo

    const int tid = threadIdx.x, lane = tid & 31, wid = tid >> 5;
    const int wm = wid / WN, wn = wid % WN;
    const int NTILES = (N_NODES + BM - 1) / BM;

    for (int i = tid; i < WSZ / 4; i += 256) {
        ((float4*)wsh)[i] = ((const float4*)Wh)[i];
        ((float4*)wsl)[i] = ((const float4*)Wl)[i];
    }

    // stage first tile (split hi/lo)
    int t = blockIdx.x;
    if (t < NTILES) {
        int r0 = t * BM;
        #pragma unroll
        for (int i = 0; i < PF; i++) {
            int f = tid + i * 256;
            int m = f >> 5, k4 = f & 31;
            int row = r0 + m;
            float4 v = make_float4(0.f, 0.f, 0.f, 0.f);
            if (row < N_NODES) v = ((const float4*)(X + (size_t)row * 128))[k4];
            float4 h, l;
            h.x = __uint_as_float(__float_as_uint(v.x) & 0xFFFFE000u); l.x = v.x - h.x;
            h.y = __uint_as_float(__float_as_uint(v.y) & 0xFFFFE000u); l.y = v.y - h.y;
            h.z = __uint_as_float(__float_as_uint(v.z) & 0xFFFFE000u); l.z = v.z - h.z;
            h.w = __uint_as_float(__float_as_uint(v.w) & 0xFFFFE000u); l.w = v.w - h.w;
            *((float4*)(xs_h + m * XROW + k4 * 4)) = h;
            *((float4*)(xs_l + m * XROW + k4 * 4)) = l;
        }
    }
    __syncthreads();

    for (; t < NTILES; t += gridDim.x) {
        const int tn = t + gridDim.x;

        // prefetch next tile into registers (LDGs overlap the MMA phase)
        float4 pf[PF];
        if (tn < NTILES) {
            int r0 = tn * BM;
            #pragma unroll
            for (int i = 0; i < PF; i++) {
                int f = tid + i * 256;
                int m = f >> 5, k4 = f & 31;
                int row = r0 + m;
                pf[i] = make_float4(0.f, 0.f, 0.f, 0.f);
                if (row < N_NODES) pf[i] = ((const float4*)(X + (size_t)row * 128))[k4];
            }
        }

        float acc[MT][4][4];
        #pragma unroll
        for (int a = 0; a < MT; a++)
            #pragma unroll
            for (int b = 0; b < 4; b++)
                #pragma unroll
                for (int c = 0; c < 4; c++) acc[a][b][c] = 0.f;

        #pragma unroll
        for (int ks = 0; ks < KS; ks++) {
            unsigned ahi[MT][4], alo[MT][4];
            #pragma unroll
            for (int mt = 0; mt < MT; mt++) {
                int r = wm * (MT * 16) + mt * 16 + (lane >> 2);
                int c = ks * 8 + (lane & 3);
                ahi[mt][0] = __float_as_uint(xs_h[r * XROW + c]);
                ahi[mt][1] = __float_as_uint(xs_h[(r + 8) * XROW + c]);
                ahi[mt][2] = __float_as_uint(xs_h[r * XROW + c + 4]);
                ahi[mt][3] = __float_as_uint(xs_h[(r + 8) * XROW + c + 4]);
                alo[mt][0] = __float_as_uint(xs_l[r * XROW + c]);
                alo[mt][1] = __float_as_uint(xs_l[(r + 8) * XROW + c]);
                alo[mt][2] = __float_as_uint(xs_l[r * XROW + c + 4]);
                alo[mt][3] = __float_as_uint(xs_l[(r + 8) * XROW + c + 4]);
            }
            unsigned bh[4][2], bl[4][2];
            #pragma unroll
            for (int p = 0; p < 2; p++) {
                int nt2 = wn * 2 + p;
                float4 vh = *((const float4*)(wsh + ((size_t)(ks * NT2 + nt2) * 32 + lane) * 4));
                float4 vl = *((const float4*)(wsl + ((size_t)(ks * NT2 + nt2) * 32 + lane) * 4));
                bh[p * 2 + 0][0] = __float_as_uint(vh.x); bh[p * 2 + 0][1] = __float_as_uint(vh.y);
                bh[p * 2 + 1][0] = __float_as_uint(vh.z); bh[p * 2 + 1][1] = __float_as_uint(vh.w);
                bl[p * 2 + 0][0] = __float_as_uint(vl.x); bl[p * 2 + 0][1] = __float_as_uint(vl.y);
                bl[p * 2 + 1][0] = __float_as_uint(vl.z); bl[p * 2 + 1][1] = __float_as_uint(vl.w);
            }
            #pragma unroll
            for (int mt = 0; mt < MT; mt++)
                #pragma unroll
                for (int nt = 0; nt < 4; nt++) {
                    MMA_TF32(acc[mt][nt], ahi[mt], bh[nt]);
                    MMA_TF32(acc[mt][nt], ahi[mt], bl[nt]);
                    MMA_TF32(acc[mt][nt], alo[mt], bh[nt]);
                }
        }

        // ---- store output tile ----
        #pragma unroll
        for (int mt = 0; mt < MT; mt++) {
            int row = t * BM + wm * (MT * 16) + mt * 16 + (lane >> 2);
            #pragma unroll
            for (int nt = 0; nt < 4; nt++) {
                int col = wn * 32 + nt * 8 + (lane & 3) * 2;
                if (row < N_NODES)
                    *(float2*)(Y + (size_t)row * N + col) = make_float2(acc[mt][nt][0], acc[mt][nt][1]);
                if (row + 8 < N_NODES)
                    *(float2*)(Y + (size_t)(row + 8) * N + col) = make_float2(acc[mt][nt][2], acc[mt][nt][3]);
            }
        }

        // ---- publish prefetched tile (split hi/lo during the sync window) ----
        __syncthreads();
        if (tn < NTILES) {
            #pragma unroll
            for (int i = 0; i < PF; i++) {
                int f = tid + i * 256;
                int m = f >> 5, k4 = f & 31;
                float4 v = pf[i], h, l;
                h.x = __uint_as_float(__float_as_uint(v.x) & 0xFFFFE000u); l.x = v.x - h.x;
                h.y = __uint_as_float(__float_as_uint(v.y) & 0xFFFFE000u); l.y = v.y - h.y;
                h.z = __uint_as_float(__float_as_uint(v.z) & 0xFFFFE000u); l.z = v.z - h.z;
                h.w = __uint_as_float(__float_as_uint(v.w) & 0xFFFFE000u); l.w = v.w - h.w;
                *((float4*)(xs_h + m * XROW + k4 * 4)) = h;
                *((float4*)(xs_l + m * XROW + k4 * 4)) = l;
            }
        }
        __syncthreads();
    }
}

// ---------------- aggregation: out[v] = sum_e norm*xw[src] + deg^-1*xw[v] + b ----------------
template <bool RELU>
__global__ void k_agg128(const float* __restrict__ xw, const float* __restrict__ bias,
                         float* __restrict__ out) {
    int w = (blockIdx.x * blockDim.x + threadIdx.x) >> 5;
    int lane = threadIdx.x & 31;
    if (w >= N_NODES) return;

    int beg = g_rowptr[w], end = g_rowptr[w + 1];
    float4 acc = make_float4(0.f, 0.f, 0.f, 0.f);

    int e = beg;
    for (; e + 8 <= end; e += 8) {
        int2 ed[8];
        #pragma unroll
        for (int u = 0; u < 8; u++) ed[u] = __ldg(&g_edge[e + u]);
        float4 t[8];
        #pragma unroll
        for (int u = 0; u < 8; u++)
            t[u] = __ldg(reinterpret_cast<const float4*>(xw + (size_t)ed[u].x * 128) + lane);
        #pragma unroll
        for (int u = 0; u < 8; u++) {
            float n = __int_as_float(ed[u].y);
            acc.x = fmaf(n, t[u].x, acc.x);
            acc.y = fmaf(n, t[u].y, acc.y);
            acc.z = fmaf(n, t[u].z, acc.z);
            acc.w = fmaf(n, t[u].w, acc.w);
        }
    }
    for (; e < end; e++) {
        int2 ed = __ldg(&g_edge[e]);
        float n = __int_as_float(ed.y);
        float4 tc = __ldg(reinterpret_cast<const float4*>(xw + (size_t)ed.x * 128) + lane);
        acc.x = fmaf(n, tc.x, acc.x);
        acc.y = fmaf(n, tc.y, acc.y);
        acc.z = fmaf(n, tc.z, acc.z);
        acc.w = fmaf(n, tc.w, acc.w);
    }

    float self = 1.0f / g_deg[w];
    float4 sv = __ldg(reinterpret_cast<const float4*>(xw + (size_t)w * 128) + lane);
    float4 bv = __ldg(reinterpret_cast<const float4*>(bias) + lane);
    acc.x = fmaf(self, sv.x, acc.x) + bv.x;
    acc.y = fmaf(self, sv.y, acc.y) + bv.y;
    acc.z = fmaf(self, sv.z, acc.z) + bv.z;
    acc.w = fmaf(self, sv.w, acc.w) + bv.w;
    if (RELU) {
        acc.x = fmaxf(acc.x, 0.f); acc.y = fmaxf(acc.y, 0.f);
        acc.z = fmaxf(acc.z, 0.f); acc.w = fmaxf(acc.w, 0.f);
    }
    *(reinterpret_cast<float4*>(out + (size_t)w * 128) + lane) = acc;
}

template <bool RELU>
__global__ void k_agg64(const float* __restrict__ xw, const float* __restrict__ bias,
                        float* __restrict__ out) {
    int w = (blockIdx.x * blockDim.x + threadIdx.x) >> 5;
    int lane = threadIdx.x & 31;
    if (w >= N_NODES) return;

    int beg = g_rowptr[w], end = g_rowptr[w + 1];
    float2 acc = make_float2(0.f, 0.f);

    int e = beg;
    for (; e + 8 <= end; e += 8) {
        int2 ed[8];
        #pragma unroll
        for (int u = 0; u < 8; u++) ed[u] = __ldg(&g_edge[e + u]);
        float2 t[8];
        #pragma unroll
        for (int u = 0; u < 8; u++)
            t[u] = __ldg(reinterpret_cast<const float2*>(xw + (size_t)ed[u].x * 64) + lane);
        #pragma unroll
        for (int u = 0; u < 8; u++) {
            float n = __int_as_float(ed[u].y);
            acc.x = fmaf(n, t[u].x, acc.x);
            acc.y = fmaf(n, t[u].y, acc.y);
        }
    }
    for (; e < end; e++) {
        int2 ed = __ldg(&g_edge[e]);
        float n = __int_as_float(ed.y);
        float2 tc = __ldg(reinterpret_cast<const float2*>(xw + (size_t)ed.x * 64) + lane);
        acc.x = fmaf(n, tc.x, acc.x);
        acc.y = fmaf(n, tc.y, acc.y);
    }

    float self = 1.0f / g_deg[w];
    float2 sv = __ldg(reinterpret_cast<const float2*>(xw + (size_t)w * 64) + lane);
    float2 bv = __ldg(reinterpret_cast<const float2*>(bias) + lane);
    acc.x = fmaf(self, sv.x, acc.x) + bv.x;
    acc.y = fmaf(self, sv.y, acc.y) + bv.y;
    if (RELU) { acc.x = fmaxf(acc.x, 0.f); acc.y = fmaxf(acc.y, 0.f); }
    *(reinterpret_cast<float2*>(out + (size_t)w * 64) + lane) = acc;
}

// ---------------- launch ----------------
extern "C" void kernel_launch(void* const* d_in, const int* in_sizes, int n_in,
                              void* d_out, int out_size) {
    const float* x  = (const float*)d_in[0];
    const void*  ei = d_in[1];
    const float* ew = (const float*)d_in[2];
    const float* W1 = (const float*)d_in[3];
    const float* b1 = (const float*)d_in[4];
    const float* W2 = (const float*)d_in[5];
    const float* b2 = (const float*)d_in[6];
    const float* W3 = (const float*)d_in[7];
    const float* b3 = (const float*)d_in[8];
    float* out = (float*)d_out;

    float* bufA; cudaGetSymbolAddress((void**)&bufA, g_bufA);
    float* bufB; cudaGetSymbolAddress((void**)&bufB, g_bufB);
    float* wh;   cudaGetSymbolAddress((void**)&wh, g_wh);
    float* wl;   cudaGetSymbolAddress((void**)&wl, g_wl);

    int nsm = 148;
    cudaDeviceGetAttribute(&nsm, cudaDevAttrMultiProcessorCount, 0);

    const int SMEM128 = (2 * 16384 + 2 * 64 * 132) * 4;  // 198656
    const int SMEM64  = (2 * 8192 + 2 * 64 * 132) * 4;   // 133120
    cudaFuncSetAttribute(k_gemm_tc<128>, cudaFuncAttributeMaxDynamicSharedMemorySize, SMEM128);
    cudaFuncSetAttribute(k_gemm_tc<64>,  cudaFuncAttributeMaxDynamicSharedMemorySize, SMEM64);

    const int nodeBlocks = (N_NODES + 255) / 256;
    const int edgeBlocks = (N_EDGES + 255) / 256;
    const int aggBlocks  = (N_NODES + 7) / 8;

    // launch order chosen so #4 (= ncu's fixed profiling window) is the layer-1 GEMM
    k_detect_init<<<nodeBlocks, 256>>>((const int*)ei);            // 1
    k_wfrag_all<<<40, 256>>>(W1, W2, W3);                          // 2
    k_deg<<<edgeBlocks, 256>>>(ei, ew);                            // 3
    k_gemm_tc<128><<<nsm, 256, SMEM128>>>(x, wh, wl, bufA);        // 4  <- profiled
    k_scan<<<1, 1024>>>();                                         // 5
    k_scatter<<<edgeBlocks, 256>>>(ei, ew);                        // 6
    k_agg128<true><<<aggBlocks, 256>>>(bufA, b1, bufB);            // 7
    k_gemm_tc<128><<<nsm, 256, SMEM128>>>(bufB, wh + 16384, wl + 16384, bufA);  // 8
    k_agg128<true><<<aggBlocks, 256>>>(bufA, b2, bufB);            // 9
    k_gemm_tc<64><<<nsm, 256, SMEM64>>>(bufB, wh + 32768, wl + 32768, bufA);    // 10
    k_agg64<false><<<aggBlocks, 256>>>(bufA, b3, out);             // 11
}

// round 8
// speedup vs baseline: 1.0134x; 1.0134x over previous
#include <cuda_runtime.h>
#include <cstdint>

#define N_NODES 100000
#define N_EDGES 1600000

// ---------------- scratch (static device globals; no allocations) ----------------
__device__ int   g_is64;
__device__ float g_deg[N_NODES];
__device__ int   g_counts[N_NODES];
__device__ int   g_rowptr[N_NODES + 1];
__device__ int   g_cursor[N_NODES];
__device__ int   g_colidx[N_EDGES];
__device__ float g_enorm[N_EDGES];
__device__ float g_bufA[(size_t)N_NODES * 128];
__device__ float g_bufB[(size_t)N_NODES * 128];
// W fragments (hi/lo): W1@0 (16384), W2@16384, W3@32768 (8192)
__device__ float g_wh[40960];
__device__ float g_wl[40960];

// ---------------- fused: dtype detection + init ----------------
__global__ void k_detect_init(const int* __restrict__ w) {
    int i = blockIdx.x * blockDim.x + threadIdx.x;
    if (i < N_NODES) { g_deg[i] = 1.0f; g_counts[i] = 0; }
    if (blockIdx.x == 0) {
        __shared__ int any;
        if (threadIdx.x == 0) any = 0;
        __syncthreads();
        const int STRIDE = N_EDGES / 4096;
        for (int t = threadIdx.x; t < 4096; t += blockDim.x) {
            int v = w[2 * (t * STRIDE) + 1];
            if (v != 0) any = 1;
        }
        __syncthreads();
        if (threadIdx.x == 0) g_is64 = any ? 0 : 1;
    }
}

__device__ __forceinline__ int load_idx(const void* ei, long long pos) {
    if (g_is64) return (int)((const long long*)ei)[pos];
    return ((const int*)ei)[pos];
}

// ---------------- prep kernels ----------------
__global__ void k_deg(const void* __restrict__ ei, const float* __restrict__ ew) {
    int e = blockIdx.x * blockDim.x + threadIdx.x;
    if (e < N_EDGES) {
        int dst = load_idx(ei, (long long)N_EDGES + e);
        atomicAdd(&g_deg[dst], ew[e]);
        atomicAdd(&g_counts[dst], 1);
    }
}

__global__ void k_scan() {
    __shared__ int sbuf[2][1024];
    const int tid = threadIdx.x;
    const int per = (N_NODES + 1023) / 1024;
    int start = tid * per;
    int end   = min(start + per, N_NODES);

    int s = 0;
    for (int i = start; i < end; i++) s += g_counts[i];

    int sel = 0;
    sbuf[0][tid] = s;
    __syncthreads();
    for (int off = 1; off < 1024; off <<= 1) {
        int v = sbuf[sel][tid];
        if (tid >= off) v += sbuf[sel][tid - off];
        sbuf[sel ^ 1][tid] = v;
        sel ^= 1;
        __syncthreads();
    }
    int incl = sbuf[sel][tid];
    int run  = incl - s;
    for (int i = start; i < end; i++) {
        g_rowptr[i] = run;
        g_cursor[i] = run;
        run += g_counts[i];
    }
    if (end == N_NODES) g_rowptr[N_NODES] = run;
}

__global__ void k_scatter(const void* __restrict__ ei, const float* __restrict__ ew) {
    int e = blockIdx.x * blockDim.x + threadIdx.x;
    if (e < N_EDGES) {
        int src = load_idx(ei, e);
        int dst = load_idx(ei, (long long)N_EDGES + e);
        int p = atomicAdd(&g_cursor[dst], 1);
        g_colidx[p] = src;
        g_enorm[p]  = rsqrtf(g_deg[src]) * ew[e] * rsqrtf(g_deg[dst]);
    }
}

// ---------------- W fragment rearrangement (all 3 weights, one launch) ----------------
template <int N>
__device__ __forceinline__ void wfrag_body(const float* __restrict__ W,
                                           float* __restrict__ outh,
                                           float* __restrict__ outl, int blk) {
    constexpr int NT2 = N / 16;
    int tid = blk * 256 + threadIdx.x;
    if (tid >= 16 * NT2 * 32) return;
    int lane = tid & 31;
    int idx  = tid >> 5;
    int nt2  = idx % NT2;
    int ks   = idx / NT2;
    #pragma unroll
    for (int u = 0; u < 2; u++) {
        #pragma unroll
        for (int j = 0; j < 2; j++) {
            int k = ks * 8 + (lane & 3) + j * 4;
            int n = (nt2 * 2 + u) * 8 + (lane >> 2);
            float v = W[k * N + n];
            unsigned hb = __float_as_uint(v) & 0xFFFFE000u;
            float hi = __uint_as_float(hb);
            outh[tid * 4 + u * 2 + j] = hi;
            outl[tid * 4 + u * 2 + j] = v - hi;
        }
    }
}

__global__ void k_wfrag_all(const float* __restrict__ W1, const float* __restrict__ W2,
                            const float* __restrict__ W3) {
    int b = blockIdx.x;
    if (b < 16)      wfrag_body<128>(W1, g_wh,         g_wl,         b);
    else if (b < 32) wfrag_body<128>(W2, g_wh + 16384, g_wl + 16384, b - 16);
    else             wfrag_body<64>(W3,  g_wh + 32768, g_wl + 32768, b - 32);
}

// ---------------- tensor-core GEMM: Y[M,N] = X[M,128] @ W[128,N], 3xTF32 ----------------
// 2 CTAs/SM, 256 threads each. X tile hi/lo pre-split in smem; W fragments read
// from global through L1 (128KB hi+lo stays L1-resident after first tile).
#define MMA_TF32(D, A, B)                                                      \
    asm volatile(                                                              \
        "mma.sync.aligned.m16n8k8.row.col.f32.tf32.tf32.f32 "                  \
        "{%0,%1,%2,%3},{%4,%5,%6,%7},{%8,%9},{%0,%1,%2,%3};\n"                 \
        : "+f"(D[0]), "+f"(D[1]), "+f"(D[2]), "+f"(D[3])                       \
        : "r"(A[0]), "r"(A[1]), "r"(A[2]), "r"(A[3]), "r"(B[0]), "r"(B[1]))

template <int N>
__global__ void __launch_bounds__(256, 2)
k_gemm_tc(const float* __restrict__ X, const float* __restrict__ Wh,
          const float* __restrict__ Wl, float* __restrict__ Y) {
    constexpr int KS = 16, NT2 = N / 16;
    constexpr int WN = N / 32;                 // warps along N
    constexpr int BM = 4096 / N;               // 32 (N=128) or 64 (N=64)
    constexpr int XROW = 132, XSZ = BM * XROW;
    constexpr int PF = BM / 8;                 // float4 per thread per X tile

    extern __shared__ float sm[];
    float* xs_h = sm;                          // [BM][XROW] hi
    float* xs_l = sm + XSZ;                    // [BM][XROW] lo

    const int tid = threadIdx.x, lane = tid & 31, wid = tid >> 5;
    const int wm = wid / WN, wn = wid % WN;
    const int NTILES = (N_NODES + BM - 1) / BM;

    // stage first tile (split hi/lo)
    int t = blockIdx.x;
    if (t < NTILES) {
        int r0 = t * BM;
        #pragma unroll
        for (int i = 0; i < PF; i++) {
            int f = tid + i * 256;
            int m = f >> 5, k4 = f & 31;
            int row = r0 + m;
            float4 v = make_float4(0.f, 0.f, 0.f, 0.f);
            if (row < N_NODES) v = ((const float4*)(X + (size_t)row * 128))[k4];
            float4 h, l;
            h.x = __uint_as_float(__float_as_uint(v.x) & 0xFFFFE000u); l.x = v.x - h.x;
            h.y = __uint_as_float(__float_as_uint(v.y) & 0xFFFFE000u); l.y = v.y - h.y;
            h.z = __uint_as_float(__float_as_uint(v.z) & 0xFFFFE000u); l.z = v.z - h.z;
            h.w = __uint_as_float(__float_as_uint(v.w) & 0xFFFFE000u); l.w = v.w - h.w;
            *((float4*)(xs_h + m * XROW + k4 * 4)) = h;
            *((float4*)(xs_l + m * XROW + k4 * 4)) = l;
        }
    }
    __syncthreads();

    for (; t < NTILES; t += gridDim.x) {
        const int tn = t + gridDim.x;

        // prefetch next tile into registers (LDGs overlap the MMA phase)
        float4 pf[PF];
        if (tn < NTILES) {
            int r0 = tn * BM;
            #pragma unroll
            for (int i = 0; i < PF; i++) {
                int f = tid + i * 256;
                int m = f >> 5, k4 = f & 31;
                int row = r0 + m;
                pf[i] = make_float4(0.f, 0.f, 0.f, 0.f);
                if (row < N_NODES) pf[i] = ((const float4*)(X + (size_t)row * 128))[k4];
            }
        }

        float acc[4][4];
        #pragma unroll
        for (int b = 0; b < 4; b++)
            #pragma unroll
            for (int c = 0; c < 4; c++) acc[b][c] = 0.f;

        #pragma unroll
        for (int ks = 0; ks < KS; ks++) {
            unsigned ahi[4], alo[4];
            {
                int r = wm * 16 + (lane >> 2);
                int c = ks * 8 + (lane & 3);
                ahi[0] = __float_as_uint(xs_h[r * XROW + c]);
                ahi[1] = __float_as_uint(xs_h[(r + 8) * XROW + c]);
                ahi[2] = __float_as_uint(xs_h[r * XROW + c + 4]);
                ahi[3] = __float_as_uint(xs_h[(r + 8) * XROW + c + 4]);
                alo[0] = __float_as_uint(xs_l[r * XROW + c]);
                alo[1] = __float_as_uint(xs_l[(r + 8) * XROW + c]);
                alo[2] = __float_as_uint(xs_l[r * XROW + c + 4]);
                alo[3] = __float_as_uint(xs_l[(r + 8) * XROW + c + 4]);
            }
            unsigned bh[4][2], bl[4][2];
            #pragma unroll
            for (int p = 0; p < 2; p++) {
                int nt2 = wn * 2 + p;
                float4 vh = __ldg((const float4*)(Wh + ((size_t)(ks * NT2 + nt2) * 32 + lane) * 4));
                float4 vl = __ldg((const float4*)(Wl + ((size_t)(ks * NT2 + nt2) * 32 + lane) * 4));
                bh[p * 2 + 0][0] = __float_as_uint(vh.x); bh[p * 2 + 0][1] = __float_as_uint(vh.y);
                bh[p * 2 + 1][0] = __float_as_uint(vh.z); bh[p * 2 + 1][1] = __float_as_uint(vh.w);
                bl[p * 2 + 0][0] = __float_as_uint(vl.x); bl[p * 2 + 0][1] = __float_as_uint(vl.y);
                bl[p * 2 + 1][0] = __float_as_uint(vl.z); bl[p * 2 + 1][1] = __float_as_uint(vl.w);
            }
            #pragma unroll
            for (int nt = 0; nt < 4; nt++) {
                MMA_TF32(acc[nt], ahi, bh[nt]);
                MMA_TF32(acc[nt], ahi, bl[nt]);
                MMA_TF32(acc[nt], alo, bh[nt]);
            }
        }

        // publish prefetched tile first (next k-loop ready ASAP), then epilogue
        __syncthreads();
        if (tn < NTILES) {
            #pragma unroll
            for (int i = 0; i < PF; i++) {
                int f = tid + i * 256;
                int m = f >> 5, k4 = f & 31;
                float4 v = pf[i], h, l;
                h.x = __uint_as_float(__float_as_uint(v.x) & 0xFFFFE000u); l.x = v.x - h.x;
                h.y = __uint_as_float(__float_as_uint(v.y) & 0xFFFFE000u); l.y = v.y - h.y;
                h.z = __uint_as_float(__float_as_uint(v.z) & 0xFFFFE000u); l.z = v.z - h.z;
                h.w = __uint_as_float(__float_as_uint(v.w) & 0xFFFFE000u); l.w = v.w - h.w;
                *((float4*)(xs_h + m * XROW + k4 * 4)) = h;
                *((float4*)(xs_l + m * XROW + k4 * 4)) = l;
            }
        }
        __syncthreads();

        // ---- store output tile (regs only; overlaps next tile's k-loop of the co-CTA) ----
        {
            int row = t * BM + wm * 16 + (lane >> 2);
            #pragma unroll
            for (int nt = 0; nt < 4; nt++) {
                int col = wn * 32 + nt * 8 + (lane & 3) * 2;
                if (row < N_NODES)
                    *(float2*)(Y + (size_t)row * N + col) = make_float2(acc[nt][0], acc[nt][1]);
                if (row + 8 < N_NODES)
                    *(float2*)(Y + (size_t)(row + 8) * N + col) = make_float2(acc[nt][2], acc[nt][3]);
            }
        }
    }
}

// ---------------- aggregation: out[v] = sum_e norm*xw[src] + deg^-1*xw[v] + b ----------------
template <bool RELU>
__global__ void k_agg128(const float* __restrict__ xw, const float* __restrict__ bias,
                         float* __restrict__ out) {
    int w = (blockIdx.x * blockDim.x + threadIdx.x) >> 5;
    int lane = threadIdx.x & 31;
    if (w >= N_NODES) return;

    int beg = g_rowptr[w], end = g_rowptr[w + 1];
    float4 acc = make_float4(0.f, 0.f, 0.f, 0.f);

    int e = beg;
    for (; e + 8 <= end; e += 8) {
        int s[8]; float n[8];
        #pragma unroll
        for (int u = 0; u < 8; u++) { s[u] = __ldg(&g_colidx[e + u]); n[u] = __ldg(&g_enorm[e + u]); }
        float4 t[8];
        #pragma unroll
        for (int u = 0; u < 8; u++)
            t[u] = __ldg(reinterpret_cast<const float4*>(xw + (size_t)s[u] * 128) + lane);
        #pragma unroll
        for (int u = 0; u < 8; u++) {
            acc.x = fmaf(n[u], t[u].x, acc.x);
            acc.y = fmaf(n[u], t[u].y, acc.y);
            acc.z = fmaf(n[u], t[u].z, acc.z);
            acc.w = fmaf(n[u], t[u].w, acc.w);
        }
    }
    for (; e < end; e++) {
        int   sc = __ldg(&g_colidx[e]);
        float nc = __ldg(&g_enorm[e]);
        float4 tc = __ldg(reinterpret_cast<const float4*>(xw + (size_t)sc * 128) + lane);
        acc.x = fmaf(nc, tc.x, acc.x);
        acc.y = fmaf(nc, tc.y, acc.y);
        acc.z = fmaf(nc, tc.z, acc.z);
        acc.w = fmaf(nc, tc.w, acc.w);
    }

    float self = 1.0f / g_deg[w];
    float4 sv = __ldg(reinterpret_cast<const float4*>(xw + (size_t)w * 128) + lane);
    float4 bv = __ldg(reinterpret_cast<const float4*>(bias) + lane);
    acc.x = fmaf(self, sv.x, acc.x) + bv.x;
    acc.y = fmaf(self, sv.y, acc.y) + bv.y;
    acc.z = fmaf(self, sv.z, acc.z) + bv.z;
    acc.w = fmaf(self, sv.w, acc.w) + bv.w;
    if (RELU) {
        acc.x = fmaxf(acc.x, 0.f); acc.y = fmaxf(acc.y, 0.f);
        acc.z = fmaxf(acc.z, 0.f); acc.w = fmaxf(acc.w, 0.f);
    }
    *(reinterpret_cast<float4*>(out + (size_t)w * 128) + lane) = acc;
}

template <bool RELU>
__global__ void k_agg64(const float* __restrict__ xw, const float* __restrict__ bias,
                        float* __restrict__ out) {
    int w = (blockIdx.x * blockDim.x + threadIdx.x) >> 5;
    int lane = threadIdx.x & 31;
    if (w >= N_NODES) return;

    int beg = g_rowptr[w], end = g_rowptr[w + 1];
    float2 acc = make_float2(0.f, 0.f);

    int e = beg;
    for (; e + 8 <= end; e += 8) {
        int s[8]; float n[8];
        #pragma unroll
        for (int u = 0; u < 8; u++) { s[u] = __ldg(&g_colidx[e + u]); n[u] = __ldg(&g_enorm[e + u]); }
        float2 t[8];
        #pragma unroll
        for (int u = 0; u < 8; u++)
            t[u] = __ldg(reinterpret_cast<const float2*>(xw + (size_t)s[u] * 64) + lane);
        #pragma unroll
        for (int u = 0; u < 8; u++) {
            acc.x = fmaf(n[u], t[u].x, acc.x);
            acc.y = fmaf(n[u], t[u].y, acc.y);
        }
    }
    for (; e < end; e++) {
        int   sc = __ldg(&g_colidx[e]);
        float nc = __ldg(&g_enorm[e]);
        float2 tc = __ldg(reinterpret_cast<const float2*>(xw + (size_t)sc * 64) + lane);
        acc.x = fmaf(nc, tc.x, acc.x);
        acc.y = fmaf(nc, tc.y, acc.y);
    }

    float self = 1.0f / g_deg[w];
    float2 sv = __ldg(reinterpret_cast<const float2*>(xw + (size_t)w * 64) + lane);
    float2 bv = __ldg(reinterpret_cast<const float2*>(bias) + lane);
    acc.x = fmaf(self, sv.x, acc.x) + bv.x;
    acc.y = fmaf(self, sv.y, acc.y) + bv.y;
    if (RELU) { acc.x = fmaxf(acc.x, 0.f); acc.y = fmaxf(acc.y, 0.f); }
    *(reinterpret_cast<float2*>(out + (size_t)w * 64) + lane) = acc;
}

// ---------------- launch ----------------
extern "C" void kernel_launch(void* const* d_in, const int* in_sizes, int n_in,
                              void* d_out, int out_size) {
    const float* x  = (const float*)d_in[0];
    const void*  ei = d_in[1];
    const float* ew = (const float*)d_in[2];
    const float* W1 = (const float*)d_in[3];
    const float* b1 = (const float*)d_in[4];
    const float* W2 = (const float*)d_in[5];
    const float* b2 = (const float*)d_in[6];
    const float* W3 = (const float*)d_in[7];
    const float* b3 = (const float*)d_in[8];
    float* out = (float*)d_out;

    float* bufA; cudaGetSymbolAddress((void**)&bufA, g_bufA);
    float* bufB; cudaGetSymbolAddress((void**)&bufB, g_bufB);
    float* wh;   cudaGetSymbolAddress((void**)&wh, g_wh);
    float* wl;   cudaGetSymbolAddress((void**)&wl, g_wl);

    int nsm = 148;
    cudaDeviceGetAttribute(&nsm, cudaDevAttrMultiProcessorCount, 0);

    const int SMEM128 = 2 * 32 * 132 * 4;   // 33792 (2 CTAs/SM fit easily)
    const int SMEM64  = 2 * 64 * 132 * 4;   // 67584
    cudaFuncSetAttribute(k_gemm_tc<128>, cudaFuncAttributeMaxDynamicSharedMemorySize, SMEM128);
    cudaFuncSetAttribute(k_gemm_tc<64>,  cudaFuncAttributeMaxDynamicSharedMemorySize, SMEM64);

    const int nodeBlocks = (N_NODES + 255) / 256;
    const int edgeBlocks = (N_EDGES + 255) / 256;
    const int aggBlocks  = (N_NODES + 7) / 8;

    // launch order chosen so #4 (= ncu's fixed profiling window) is the layer-1 GEMM
    k_detect_init<<<nodeBlocks, 256>>>((const int*)ei);            // 1
    k_wfrag_all<<<40, 256>>>(W1, W2, W3);                          // 2
    k_deg<<<edgeBlocks, 256>>>(ei, ew);                            // 3
    k_gemm_tc<128><<<2 * nsm, 256, SMEM128>>>(x, wh, wl, bufA);    // 4  <- profiled
    k_scan<<<1, 1024>>>();                                         // 5
    k_scatter<<<edgeBlocks, 256>>>(ei, ew);                        // 6
    k_agg128<true><<<aggBlocks, 256>>>(bufA, b1, bufB);            // 7
    k_gemm_tc<128><<<2 * nsm, 256, SMEM128>>>(bufB, wh + 16384, wl + 16384, bufA);  // 8
    k_agg128<true><<<aggBlocks, 256>>>(bufA, b2, bufB);            // 9
    k_gemm_tc<64><<<2 * nsm, 256, SMEM64>>>(bufB, wh + 32768, wl + 32768, bufA);    // 10
    k_agg64<false><<<aggBlocks, 256>>>(bufA, b3, out);             // 11
}

// round 9
// speedup vs baseline: 1.1241x; 1.1093x over previous
#include <cuda_runtime.h>
#include <cuda_bf16.h>
#include <cstdint>

#define N_NODES 100000
#define N_EDGES 1600000

// ---------------- scratch (static device globals; no allocations) ----------------
__device__ int   g_is64;
__device__ float g_deg[N_NODES];
__device__ int   g_counts[N_NODES];
__device__ int   g_rowptr[N_NODES + 1];
__device__ int   g_cursor[N_NODES];
__device__ int   g_colidx[N_EDGES];
__device__ float g_enorm[N_EDGES];
__device__ float g_bufA[(size_t)N_NODES * 128];
__device__ float g_bufB[(size_t)N_NODES * 128];
// bf16 W fragments (hi/lo), packed bf16x2 words: W1@0 (8192), W2@8192, W3@16384 (4096)
__device__ unsigned g_wfh[20480];
__device__ unsigned g_wfl[20480];

__device__ __forceinline__ unsigned bf16pack(float a, float b) {
    unsigned short ha = __bfloat16_as_ushort(__float2bfloat16(a));
    unsigned short hb = __bfloat16_as_ushort(__float2bfloat16(b));
    return (unsigned)ha | ((unsigned)hb << 16);
}

// ---------------- fused: dtype detection + init ----------------
__global__ void k_detect_init(const int* __restrict__ w) {
    int i = blockIdx.x * blockDim.x + threadIdx.x;
    if (i < N_NODES) { g_deg[i] = 1.0f; g_counts[i] = 0; }
    if (blockIdx.x == 0) {
        __shared__ int any;
        if (threadIdx.x == 0) any = 0;
        __syncthreads();
        const int STRIDE = N_EDGES / 4096;
        for (int t = threadIdx.x; t < 4096; t += blockDim.x) {
            int v = w[2 * (t * STRIDE) + 1];
            if (v != 0) any = 1;
        }
        __syncthreads();
        if (threadIdx.x == 0) g_is64 = any ? 0 : 1;
    }
}

__device__ __forceinline__ int load_idx(const void* ei, long long pos) {
    if (g_is64) return (int)((const long long*)ei)[pos];
    return ((const int*)ei)[pos];
}

// ---------------- prep kernels ----------------
__global__ void k_deg(const void* __restrict__ ei, const float* __restrict__ ew) {
    int e = blockIdx.x * blockDim.x + threadIdx.x;
    if (e < N_EDGES) {
        int dst = load_idx(ei, (long long)N_EDGES + e);
        atomicAdd(&g_deg[dst], ew[e]);
        atomicAdd(&g_counts[dst], 1);
    }
}

__global__ void k_scan() {
    __shared__ int sbuf[2][1024];
    const int tid = threadIdx.x;
    const int per = (N_NODES + 1023) / 1024;
    int start = tid * per;
    int end   = min(start + per, N_NODES);

    int s = 0;
    for (int i = start; i < end; i++) s += g_counts[i];

    int sel = 0;
    sbuf[0][tid] = s;
    __syncthreads();
    for (int off = 1; off < 1024; off <<= 1) {
        int v = sbuf[sel][tid];
        if (tid >= off) v += sbuf[sel][tid - off];
        sbuf[sel ^ 1][tid] = v;
        sel ^= 1;
        __syncthreads();
    }
    int incl = sbuf[sel][tid];
    int run  = incl - s;
    for (int i = start; i < end; i++) {
        g_rowptr[i] = run;
        g_cursor[i] = run;
        run += g_counts[i];
    }
    if (end == N_NODES) g_rowptr[N_NODES] = run;
}

__global__ void k_scatter(const void* __restrict__ ei, const float* __restrict__ ew) {
    int e = blockIdx.x * blockDim.x + threadIdx.x;
    if (e < N_EDGES) {
        int src = load_idx(ei, e);
        int dst = load_idx(ei, (long long)N_EDGES + e);
        int p = atomicAdd(&g_cursor[dst], 1);
        g_colidx[p] = src;
        g_enorm[p]  = rsqrtf(g_deg[src]) * ew[e] * rsqrtf(g_deg[dst]);
    }
}

// ---------------- W fragment rearrangement (bf16 hi/lo, all 3 weights) ----------------
// For mma.m16n8k16.row.col, B col-major fragment per lane:
//   reg0 = {B[k0][n], B[k0+1][n]}, reg1 = {B[k0+8][n], B[k0+9][n]}
//   k0 = ks*16 + (lane&3)*2, n = nt*8 + (lane>>2)
template <int N>
__device__ __forceinline__ void wfrag_body(const float* __restrict__ W,
                                           unsigned* __restrict__ outh,
                                           unsigned* __restrict__ outl, int blk) {
    constexpr int NT = N / 8;
    int tid = blk * 256 + threadIdx.x;
    if (tid >= 8 * NT * 32) return;
    int lane = tid & 31;
    int idx  = tid >> 5;
    int nt   = idx % NT;
    int ks   = idx / NT;
    int k0   = ks * 16 + (lane & 3) * 2;
    int n    = nt * 8 + (lane >> 2);
    float v[4] = { W[k0 * N + n], W[(k0 + 1) * N + n],
                   W[(k0 + 8) * N + n], W[(k0 + 9) * N + n] };
    float h[4], l[4];
    #pragma unroll
    for (int i = 0; i < 4; i++) {
        h[i] = __bfloat162float(__float2bfloat16(v[i]));
        l[i] = v[i] - h[i];
    }
    outh[tid * 2 + 0] = bf16pack(h[0], h[1]);
    outh[tid * 2 + 1] = bf16pack(h[2], h[3]);
    outl[tid * 2 + 0] = bf16pack(l[0], l[1]);
    outl[tid * 2 + 1] = bf16pack(l[2], l[3]);
}

__global__ void k_wfrag_all(const float* __restrict__ W1, const float* __restrict__ W2,
                            const float* __restrict__ W3) {
    int b = blockIdx.x;
    if (b < 16)      wfrag_body<128>(W1, g_wfh,         g_wfl,         b);
    else if (b < 32) wfrag_body<128>(W2, g_wfh + 8192,  g_wfl + 8192,  b - 16);
    else             wfrag_body<64>(W3,  g_wfh + 16384, g_wfl + 16384, b - 32);
}

// ---------------- tensor-core GEMM: Y[M,N] = X[M,128] @ W[128,N], 3xBF16 ----------------
// mma.m16n8k16.bf16: half the instructions, double FLOPs/instr vs tf32 k8.
#define MMA_BF16(D, A, B)                                                      \
    asm volatile(                                                              \
        "mma.sync.aligned.m16n8k16.row.col.f32.bf16.bf16.f32 "                 \
        "{%0,%1,%2,%3},{%4,%5,%6,%7},{%8,%9},{%0,%1,%2,%3};\n"                 \
        : "+f"(D[0]), "+f"(D[1]), "+f"(D[2]), "+f"(D[3])                       \
        : "r"(A[0]), "r"(A[1]), "r"(A[2]), "r"(A[3]), "r"(B[0]), "r"(B[1]))

template <int N>
__global__ void __launch_bounds__(256, 2)
k_gemm_tc(const float* __restrict__ X, const unsigned* __restrict__ Wh,
          const unsigned* __restrict__ Wl, float* __restrict__ Y) {
    constexpr int KC = 8;                        // K=128 / 16
    constexpr int NT = N / 8;
    constexpr int WN = N / 32;                   // warps along N (4 or 2), 4 nt each
    constexpr int MT = WN / 2;                   // m-tiles per warp (2 or 1)
    constexpr int BM = 64;
    constexpr int XROWW = 68;                    // bf16x2 words per row (64 + 4 pad)
    constexpr int XSZ = BM * XROWW;
    constexpr int PF = 8;                        // float4 per thread per X tile

    extern __shared__ unsigned smu[];
    unsigned* xs_h = smu;                        // [BM][XROWW] bf16x2 hi
    unsigned* xs_l = smu + XSZ;                  // [BM][XROWW] bf16x2 lo

    const int tid = threadIdx.x, lane = tid & 31, wid = tid >> 5;
    const int wm = wid / WN, wn = wid % WN;
    const int NTILES = (N_NODES + BM - 1) / BM;

    // stage first tile
    int t = blockIdx.x;
    if (t < NTILES) {
        int r0 = t * BM;
        #pragma unroll
        for (int i = 0; i < PF; i++) {
            int f = tid + i * 256;
            int m = f >> 5, k4 = f & 31;
            int row = r0 + m;
            float4 v = make_float4(0.f, 0.f, 0.f, 0.f);
            if (row < N_NODES) v = ((const float4*)(X + (size_t)row * 128))[k4];
            float hx = __bfloat162float(__float2bfloat16(v.x));
            float hy = __bfloat162float(__float2bfloat16(v.y));
            float hz = __bfloat162float(__float2bfloat16(v.z));
            float hw = __bfloat162float(__float2bfloat16(v.w));
            xs_h[m * XROWW + k4 * 2 + 0] = bf16pack(hx, hy);
            xs_h[m * XROWW + k4 * 2 + 1] = bf16pack(hz, hw);
            xs_l[m * XROWW + k4 * 2 + 0] = bf16pack(v.x - hx, v.y - hy);
            xs_l[m * XROWW + k4 * 2 + 1] = bf16pack(v.z - hz, v.w - hw);
        }
    }
    __syncthreads();

    for (; t < NTILES; t += gridDim.x) {
        const int tn = t + gridDim.x;

        // prefetch next tile into registers (LDGs overlap the MMA phase)
        float4 pf[PF];
        if (tn < NTILES) {
            int r0 = tn * BM;
            #pragma unroll
            for (int i = 0; i < PF; i++) {
                int f = tid + i * 256;
                int m = f >> 5, k4 = f & 31;
                int row = r0 + m;
                pf[i] = make_float4(0.f, 0.f, 0.f, 0.f);
                if (row < N_NODES) pf[i] = ((const float4*)(X + (size_t)row * 128))[k4];
            }
        }

        float acc[MT][4][4];
        #pragma unroll
        for (int a = 0; a < MT; a++)
            #pragma unroll
            for (int b = 0; b < 4; b++)
                #pragma unroll
                for (int c = 0; c < 4; c++) acc[a][b][c] = 0.f;

        #pragma unroll
        for (int ks = 0; ks < KC; ks++) {
            const int p0 = ks * 8 + (lane & 3);
            unsigned ahi[MT][4], alo[MT][4];
            #pragma unroll
            for (int mt = 0; mt < MT; mt++) {
                int r = wm * (MT * 16) + mt * 16 + (lane >> 2);
                ahi[mt][0] = xs_h[r * XROWW + p0];
                ahi[mt][1] = xs_h[(r + 8) * XROWW + p0];
                ahi[mt][2] = xs_h[r * XROWW + p0 + 4];
                ahi[mt][3] = xs_h[(r + 8) * XROWW + p0 + 4];
                alo[mt][0] = xs_l[r * XROWW + p0];
                alo[mt][1] = xs_l[(r + 8) * XROWW + p0];
                alo[mt][2] = xs_l[r * XROWW + p0 + 4];
                alo[mt][3] = xs_l[(r + 8) * XROWW + p0 + 4];
            }
            unsigned bh[4][2], bl[4][2];
            #pragma unroll
            for (int j = 0; j < 4; j++) {
                int nt = wn * 4 + j;
                uint2 vh = __ldg((const uint2*)(Wh + ((size_t)(ks * NT + nt) * 32 + lane) * 2));
                uint2 vl = __ldg((const uint2*)(Wl + ((size_t)(ks * NT + nt) * 32 + lane) * 2));
                bh[j][0] = vh.x; bh[j][1] = vh.y;
                bl[j][0] = vl.x; bl[j][1] = vl.y;
            }
            #pragma unroll
            for (int mt = 0; mt < MT; mt++)
                #pragma unroll
                for (int j = 0; j < 4; j++) {
                    MMA_BF16(acc[mt][j], ahi[mt], bh[j]);
                    MMA_BF16(acc[mt][j], ahi[mt], bl[j]);
                    MMA_BF16(acc[mt][j], alo[mt], bh[j]);
                }
        }

        // publish prefetched tile first, then epilogue
        __syncthreads();
        if (tn < NTILES) {
            #pragma unroll
            for (int i = 0; i < PF; i++) {
                int f = tid + i * 256;
                int m = f >> 5, k4 = f & 31;
                float4 v = pf[i];
                float hx = __bfloat162float(__float2bfloat16(v.x));
                float hy = __bfloat162float(__float2bfloat16(v.y));
                float hz = __bfloat162float(__float2bfloat16(v.z));
                float hw = __bfloat162float(__float2bfloat16(v.w));
                xs_h[m * XROWW + k4 * 2 + 0] = bf16pack(hx, hy);
                xs_h[m * XROWW + k4 * 2 + 1] = bf16pack(hz, hw);
                xs_l[m * XROWW + k4 * 2 + 0] = bf16pack(v.x - hx, v.y - hy);
                xs_l[m * XROWW + k4 * 2 + 1] = bf16pack(v.z - hz, v.w - hw);
            }
        }
        __syncthreads();

        // store output tile
        #pragma unroll
        for (int mt = 0; mt < MT; mt++) {
            int row = t * BM + wm * (MT * 16) + mt * 16 + (lane >> 2);
            #pragma unroll
            for (int j = 0; j < 4; j++) {
                int col = wn * 32 + j * 8 + (lane & 3) * 2;
                if (row < N_NODES)
                    *(float2*)(Y + (size_t)row * N + col) = make_float2(acc[mt][j][0], acc[mt][j][1]);
                if (row + 8 < N_NODES)
                    *(float2*)(Y + (size_t)(row + 8) * N + col) = make_float2(acc[mt][j][2], acc[mt][j][3]);
            }
        }
    }
}

// ---------------- aggregation: out[v] = sum_e norm*xw[src] + deg^-1*xw[v] + b ----------------
template <bool RELU>
__global__ void k_agg128(const float* __restrict__ xw, const float* __restrict__ bias,
                         float* __restrict__ out) {
    int w = (blockIdx.x * blockDim.x + threadIdx.x) >> 5;
    int lane = threadIdx.x & 31;
    if (w >= N_NODES) return;

    int beg = g_rowptr[w], end = g_rowptr[w + 1];
    float4 acc = make_float4(0.f, 0.f, 0.f, 0.f);

    int e = beg;
    for (; e + 8 <= end; e += 8) {
        int s[8]; float n[8];
        #pragma unroll
        for (int u = 0; u < 8; u++) { s[u] = __ldg(&g_colidx[e + u]); n[u] = __ldg(&g_enorm[e + u]); }
        float4 t[8];
        #pragma unroll
        for (int u = 0; u < 8; u++)
            t[u] = __ldg(reinterpret_cast<const float4*>(xw + (size_t)s[u] * 128) + lane);
        #pragma unroll
        for (int u = 0; u < 8; u++) {
            acc.x = fmaf(n[u], t[u].x, acc.x);
            acc.y = fmaf(n[u], t[u].y, acc.y);
            acc.z = fmaf(n[u], t[u].z, acc.z);
            acc.w = fmaf(n[u], t[u].w, acc.w);
        }
    }
    for (; e < end; e++) {
        int   sc = __ldg(&g_colidx[e]);
        float nc = __ldg(&g_enorm[e]);
        float4 tc = __ldg(reinterpret_cast<const float4*>(xw + (size_t)sc * 128) + lane);
        acc.x = fmaf(nc, tc.x, acc.x);
        acc.y = fmaf(nc, tc.y, acc.y);
        acc.z = fmaf(nc, tc.z, acc.z);
        acc.w = fmaf(nc, tc.w, acc.w);
    }

    float self = 1.0f / g_deg[w];
    float4 sv = __ldg(reinterpret_cast<const float4*>(xw + (size_t)w * 128) + lane);
    float4 bv = __ldg(reinterpret_cast<const float4*>(bias) + lane);
    acc.x = fmaf(self, sv.x, acc.x) + bv.x;
    acc.y = fmaf(self, sv.y, acc.y) + bv.y;
    acc.z = fmaf(self, sv.z, acc.z) + bv.z;
    acc.w = fmaf(self, sv.w, acc.w) + bv.w;
    if (RELU) {
        acc.x = fmaxf(acc.x, 0.f); acc.y = fmaxf(acc.y, 0.f);
        acc.z = fmaxf(acc.z, 0.f); acc.w = fmaxf(acc.w, 0.f);
    }
    *(reinterpret_cast<float4*>(out + (size_t)w * 128) + lane) = acc;
}

template <bool RELU>
__global__ void k_agg64(const float* __restrict__ xw, const float* __restrict__ bias,
                        float* __restrict__ out) {
    int w = (blockIdx.x * blockDim.x + threadIdx.x) >> 5;
    int lane = threadIdx.x & 31;
    if (w >= N_NODES) return;

    int beg = g_rowptr[w], end = g_rowptr[w + 1];
    float2 acc = make_float2(0.f, 0.f);

    int e = beg;
    for (; e + 8 <= end; e += 8) {
        int s[8]; float n[8];
        #pragma unroll
        for (int u = 0; u < 8; u++) { s[u] = __ldg(&g_colidx[e + u]); n[u] = __ldg(&g_enorm[e + u]); }
        float2 t[8];
        #pragma unroll
        for (int u = 0; u < 8; u++)
            t[u] = __ldg(reinterpret_cast<const float2*>(xw + (size_t)s[u] * 64) + lane);
        #pragma unroll
        for (int u = 0; u < 8; u++) {
            acc.x = fmaf(n[u], t[u].x, acc.x);
            acc.y = fmaf(n[u], t[u].y, acc.y);
        }
    }
    for (; e < end; e++) {
        int   sc = __ldg(&g_colidx[e]);
        float nc = __ldg(&g_enorm[e]);
        float2 tc = __ldg(reinterpret_cast<const float2*>(xw + (size_t)sc * 64) + lane);
        acc.x = fmaf(nc, tc.x, acc.x);
        acc.y = fmaf(nc, tc.y, acc.y);
    }

    float self = 1.0f / g_deg[w];
    float2 sv = __ldg(reinterpret_cast<const float2*>(xw + (size_t)w * 64) + lane);
    float2 bv = __ldg(reinterpret_cast<const float2*>(bias) + lane);
    acc.x = fmaf(self, sv.x, acc.x) + bv.x;
    acc.y = fmaf(self, sv.y, acc.y) + bv.y;
    if (RELU) { acc.x = fmaxf(acc.x, 0.f); acc.y = fmaxf(acc.y, 0.f); }
    *(reinterpret_cast<float2*>(out + (size_t)w * 64) + lane) = acc;
}

// ---------------- launch ----------------
extern "C" void kernel_launch(void* const* d_in, const int* in_sizes, int n_in,
                              void* d_out, int out_size) {
    const float* x  = (const float*)d_in[0];
    const void*  ei = d_in[1];
    const float* ew = (const float*)d_in[2];
    const float* W1 = (const float*)d_in[3];
    const float* b1 = (const float*)d_in[4];
    const float* W2 = (const float*)d_in[5];
    const float* b2 = (const float*)d_in[6];
    const float* W3 = (const float*)d_in[7];
    const float* b3 = (const float*)d_in[8];
    float* out = (float*)d_out;

    float*    bufA; cudaGetSymbolAddress((void**)&bufA, g_bufA);
    float*    bufB; cudaGetSymbolAddress((void**)&bufB, g_bufB);
    unsigned* wfh;  cudaGetSymbolAddress((void**)&wfh, g_wfh);
    unsigned* wfl;  cudaGetSymbolAddress((void**)&wfl, g_wfl);

    int nsm = 148;
    cudaDeviceGetAttribute(&nsm, cudaDevAttrMultiProcessorCount, 0);

    const int SMEM = 2 * 64 * 68 * 4;   // 34816 B (hi + lo X tile), 2 CTAs/SM
    cudaFuncSetAttribute(k_gemm_tc<128>, cudaFuncAttributeMaxDynamicSharedMemorySize, SMEM);
    cudaFuncSetAttribute(k_gemm_tc<64>,  cudaFuncAttributeMaxDynamicSharedMemorySize, SMEM);

    const int nodeBlocks = (N_NODES + 255) / 256;
    const int edgeBlocks = (N_EDGES + 255) / 256;
    const int aggBlocks  = (N_NODES + 7) / 8;

    // launch order chosen so #4 (= ncu's fixed profiling window) is the layer-1 GEMM
    k_detect_init<<<nodeBlocks, 256>>>((const int*)ei);            // 1
    k_wfrag_all<<<40, 256>>>(W1, W2, W3);                          // 2
    k_deg<<<edgeBlocks, 256>>>(ei, ew);                            // 3
    k_gemm_tc<128><<<2 * nsm, 256, SMEM>>>(x, wfh, wfl, bufA);     // 4  <- profiled
    k_scan<<<1, 1024>>>();                                         // 5
    k_scatter<<<edgeBlocks, 256>>>(ei, ew);                        // 6
    k_agg128<true><<<aggBlocks, 256>>>(bufA, b1, bufB);            // 7
    k_gemm_tc<128><<<2 * nsm, 256, SMEM>>>(bufB, wfh + 8192, wfl + 8192, bufA);   // 8
    k_agg128<true><<<aggBlocks, 256>>>(bufA, b2, bufB);            // 9
    k_gemm_tc<64><<<2 * nsm, 256, SMEM>>>(bufB, wfh + 16384, wfl + 16384, bufA);  // 10
    k_agg64<false><<<aggBlocks, 256>>>(bufA, b3, out);             // 11
}